// round 4
// baseline (speedup 1.0000x reference)
#include <cuda_runtime.h>

#define N0 500000
#define N1 100000
#define N2 10000
#define IN_CH 128
#define HID 16
#define OUT_CH 64
#define E1MAX 2000000
#define E2MAX 400000
#define SCAN_B 1024

// ---------------- scratch (device globals) ----------------
__device__ float g_xp[(size_t)N0 * HID];     // x @ W1
__device__ float g_h1[(size_t)N1 * HID];     // relu(mean1 + b1)
__device__ float g_mean2[(size_t)N2 * HID];  // layer-2 means
__device__ int g_csr1[E1MAX];
__device__ int g_csr2[E2MAX];
__device__ int g_cnt1[N1], g_offs1[N1], g_cur1[N1];
__device__ int g_cnt2[N2], g_offs2[N2], g_cur2[N2];
__device__ int g_part1[128], g_part2[128];

__device__ __forceinline__ unsigned long long bcast2(float v) {
    unsigned long long r;
    asm("mov.b64 %0, {%1,%1};" : "=l"(r) : "f"(v));
    return r;
}
__device__ __forceinline__ void fma2(unsigned long long& acc, unsigned long long a,
                                     unsigned long long b) {
    asm("fma.rn.f32x2 %0, %1, %2, %0;" : "+l"(acc) : "l"(a), "l"(b));
}

// ---------------------------------------------------------------------------
__global__ void k_zero() {
    int i = blockIdx.x * blockDim.x + threadIdx.x;
    if (i < N1) g_cnt1[i] = 0;
    if (i < N2) g_cnt2[i] = 0;
}

// xp = x @ W1 with packed f32x2 FMAs; W1 pairs staged in smem
__global__ void k_project(const float* __restrict__ x, const float* __restrict__ W1) {
    __shared__ unsigned long long w2[IN_CH * 8];  // [k][j-pair]
    for (int i = threadIdx.x; i < IN_CH * 8; i += blockDim.x) {
        int k = i >> 3, jp = i & 7;
        float lo = W1[k * HID + jp * 2];
        float hi = W1[k * HID + jp * 2 + 1];
        unsigned long long p;
        asm("mov.b64 %0, {%1,%2};" : "=l"(p) : "f"(lo), "f"(hi));
        w2[i] = p;
    }
    __syncthreads();
    int row = blockIdx.x * blockDim.x + threadIdx.x;
    if (row >= N0) return;

    unsigned long long acc[8];
#pragma unroll
    for (int j = 0; j < 8; j++) acc[j] = 0ull;  // pair of +0.0f

    const float4* xr = (const float4*)(x + (size_t)row * IN_CH);
#pragma unroll 4
    for (int k4 = 0; k4 < IN_CH / 4; k4++) {
        float4 v = xr[k4];
        int k = k4 * 4;
        unsigned long long xx;
        xx = bcast2(v.x);
#pragma unroll
        for (int j = 0; j < 8; j++) fma2(acc[j], xx, w2[(k + 0) * 8 + j]);
        xx = bcast2(v.y);
#pragma unroll
        for (int j = 0; j < 8; j++) fma2(acc[j], xx, w2[(k + 1) * 8 + j]);
        xx = bcast2(v.z);
#pragma unroll
        for (int j = 0; j < 8; j++) fma2(acc[j], xx, w2[(k + 2) * 8 + j]);
        xx = bcast2(v.w);
#pragma unroll
        for (int j = 0; j < 8; j++) fma2(acc[j], xx, w2[(k + 3) * 8 + j]);
    }
    float o[HID];
#pragma unroll
    for (int j = 0; j < 8; j++)
        asm("mov.b64 {%0,%1}, %2;" : "=f"(o[2 * j]), "=f"(o[2 * j + 1]) : "l"(acc[j]));
    float4* op = (float4*)(g_xp + (size_t)row * HID);
#pragma unroll
    for (int q = 0; q < 4; q++)
        op[q] = make_float4(o[q * 4], o[q * 4 + 1], o[q * 4 + 2], o[q * 4 + 3]);
}

// ---------------- CSR build ----------------
__global__ void k_hist(const int* __restrict__ dst, int E, int* __restrict__ cnt) {
    int e = blockIdx.x * blockDim.x + threadIdx.x;
    if (e < E) atomicAdd(&cnt[dst[e]], 1);
}

// per-block exclusive scan of cnt -> offs, block totals -> partials
__global__ void k_scan_block(const int* __restrict__ cnt, int* __restrict__ offs,
                             int* __restrict__ partials, int n) {
    __shared__ int wtot[32];
    int i = blockIdx.x * SCAN_B + threadIdx.x;
    int lane = threadIdx.x & 31, wid = threadIdx.x >> 5;
    int v = (i < n) ? cnt[i] : 0;
    int incl = v;
#pragma unroll
    for (int off = 1; off < 32; off <<= 1) {
        int t = __shfl_up_sync(0xffffffffu, incl, off);
        if (lane >= off) incl += t;
    }
    if (lane == 31) wtot[wid] = incl;
    __syncthreads();
    if (wid == 0) {
        int t = wtot[lane];
#pragma unroll
        for (int off = 1; off < 32; off <<= 1) {
            int u = __shfl_up_sync(0xffffffffu, t, off);
            if (lane >= off) t += u;
        }
        wtot[lane] = t;
    }
    __syncthreads();
    int base = wid ? wtot[wid - 1] : 0;
    if (i < n) offs[i] = base + incl - v;
    if (threadIdx.x == 0) partials[blockIdx.x] = wtot[31];
}

// single-block serial scan of block totals (nb <= 128)
__global__ void k_scan_partials(int* __restrict__ partials, int nb) {
    __shared__ int s[128];
    int t = threadIdx.x;
    if (t < nb) s[t] = partials[t];
    __syncthreads();
    if (t == 0) {
        int run = 0;
        for (int b = 0; b < nb; b++) { int v = s[b]; s[b] = run; run += v; }
    }
    __syncthreads();
    if (t < nb) partials[t] = s[t];
}

__global__ void k_scan_add(int* __restrict__ offs, int* __restrict__ cur,
                           const int* __restrict__ partials, int n) {
    int i = blockIdx.x * SCAN_B + threadIdx.x;
    if (i < n) {
        int o = offs[i] + partials[blockIdx.x];
        offs[i] = o;
        cur[i] = o;
    }
}

__global__ void k_permute(const int* __restrict__ src, const int* __restrict__ dst, int E,
                          int* __restrict__ cur, int* __restrict__ csr) {
    int e = blockIdx.x * blockDim.x + threadIdx.x;
    if (e >= E) return;
    int pos = atomicAdd(&cur[dst[e]], 1);
    csr[pos] = src[e];
}

// ---------------- gather-reduce ----------------
// h1 = relu(mean(xp over neighbors) + b1)
__global__ void k_gather1(const float* __restrict__ b1) {
    int t = blockIdx.x * blockDim.x + threadIdx.x;
    if (t >= N1) return;
    int begin = g_offs1[t];
    int c = g_cnt1[t];
    float4 a0 = {0, 0, 0, 0}, a1 = a0, a2 = a0, a3 = a0;
    for (int i = 0; i < c; i++) {
        int s = g_csr1[begin + i];
        const float4* xr = (const float4*)(g_xp + (size_t)s * HID);
        float4 v0 = xr[0], v1 = xr[1], v2 = xr[2], v3 = xr[3];
        a0.x += v0.x; a0.y += v0.y; a0.z += v0.z; a0.w += v0.w;
        a1.x += v1.x; a1.y += v1.y; a1.z += v1.z; a1.w += v1.w;
        a2.x += v2.x; a2.y += v2.y; a2.z += v2.z; a2.w += v2.w;
        a3.x += v3.x; a3.y += v3.y; a3.z += v3.z; a3.w += v3.w;
    }
    float inv = 1.0f / (float)max(c, 1);
    float4* hp = (float4*)(g_h1 + (size_t)t * HID);
    float4 r;
    r.x = fmaxf(fmaf(a0.x, inv, __ldg(b1 + 0)), 0.f);
    r.y = fmaxf(fmaf(a0.y, inv, __ldg(b1 + 1)), 0.f);
    r.z = fmaxf(fmaf(a0.z, inv, __ldg(b1 + 2)), 0.f);
    r.w = fmaxf(fmaf(a0.w, inv, __ldg(b1 + 3)), 0.f);
    hp[0] = r;
    r.x = fmaxf(fmaf(a1.x, inv, __ldg(b1 + 4)), 0.f);
    r.y = fmaxf(fmaf(a1.y, inv, __ldg(b1 + 5)), 0.f);
    r.z = fmaxf(fmaf(a1.z, inv, __ldg(b1 + 6)), 0.f);
    r.w = fmaxf(fmaf(a1.w, inv, __ldg(b1 + 7)), 0.f);
    hp[1] = r;
    r.x = fmaxf(fmaf(a2.x, inv, __ldg(b1 + 8)), 0.f);
    r.y = fmaxf(fmaf(a2.y, inv, __ldg(b1 + 9)), 0.f);
    r.z = fmaxf(fmaf(a2.z, inv, __ldg(b1 + 10)), 0.f);
    r.w = fmaxf(fmaf(a2.w, inv, __ldg(b1 + 11)), 0.f);
    hp[2] = r;
    r.x = fmaxf(fmaf(a3.x, inv, __ldg(b1 + 12)), 0.f);
    r.y = fmaxf(fmaf(a3.y, inv, __ldg(b1 + 13)), 0.f);
    r.z = fmaxf(fmaf(a3.z, inv, __ldg(b1 + 14)), 0.f);
    r.w = fmaxf(fmaf(a3.w, inv, __ldg(b1 + 15)), 0.f);
    hp[3] = r;
}

// mean2 = mean(h1 over neighbors)
__global__ void k_gather2() {
    int t = blockIdx.x * blockDim.x + threadIdx.x;
    if (t >= N2) return;
    int begin = g_offs2[t];
    int c = g_cnt2[t];
    float4 a0 = {0, 0, 0, 0}, a1 = a0, a2 = a0, a3 = a0;
    for (int i = 0; i < c; i++) {
        int s = g_csr2[begin + i];
        const float4* xr = (const float4*)(g_h1 + (size_t)s * HID);
        float4 v0 = xr[0], v1 = xr[1], v2 = xr[2], v3 = xr[3];
        a0.x += v0.x; a0.y += v0.y; a0.z += v0.z; a0.w += v0.w;
        a1.x += v1.x; a1.y += v1.y; a1.z += v1.z; a1.w += v1.w;
        a2.x += v2.x; a2.y += v2.y; a2.z += v2.z; a2.w += v2.w;
        a3.x += v3.x; a3.y += v3.y; a3.z += v3.z; a3.w += v3.w;
    }
    float inv = 1.0f / (float)max(c, 1);
    float4* mp = (float4*)(g_mean2 + (size_t)t * HID);
    mp[0] = make_float4(a0.x * inv, a0.y * inv, a0.z * inv, a0.w * inv);
    mp[1] = make_float4(a1.x * inv, a1.y * inv, a1.z * inv, a1.w * inv);
    mp[2] = make_float4(a2.x * inv, a2.y * inv, a2.z * inv, a2.w * inv);
    mp[3] = make_float4(a3.x * inv, a3.y * inv, a3.z * inv, a3.w * inv);
}

// out = log_softmax(mean2 @ W2 + b2), warp per row
__global__ void k_out(const float* __restrict__ W2, const float* __restrict__ b2,
                      float* __restrict__ out) {
    __shared__ float w[HID * OUT_CH];
    __shared__ float bb[OUT_CH];
    for (int i = threadIdx.x; i < HID * OUT_CH; i += blockDim.x) w[i] = W2[i];
    if (threadIdx.x < OUT_CH) bb[threadIdx.x] = b2[threadIdx.x];
    __syncthreads();

    int warp = threadIdx.x >> 5;
    int lane = threadIdx.x & 31;
    int row = blockIdx.x * (blockDim.x / 32) + warp;
    if (row >= N2) return;

    float m[HID];
#pragma unroll
    for (int k = 0; k < HID; k++) m[k] = g_mean2[(size_t)row * HID + k];

    float o0 = bb[lane];
    float o1 = bb[lane + 32];
#pragma unroll
    for (int k = 0; k < HID; k++) {
        o0 += m[k] * w[k * OUT_CH + lane];
        o1 += m[k] * w[k * OUT_CH + lane + 32];
    }

    float mx = fmaxf(o0, o1);
#pragma unroll
    for (int off = 16; off; off >>= 1) mx = fmaxf(mx, __shfl_xor_sync(0xffffffffu, mx, off));
    float s = __expf(o0 - mx) + __expf(o1 - mx);
#pragma unroll
    for (int off = 16; off; off >>= 1) s += __shfl_xor_sync(0xffffffffu, s, off);
    float lse = mx + __logf(s);

    out[(size_t)row * OUT_CH + lane] = o0 - lse;
    out[(size_t)row * OUT_CH + lane + 32] = o1 - lse;
}

// ---------------------------------------------------------------------------
extern "C" void kernel_launch(void* const* d_in, const int* in_sizes, int n_in,
                              void* d_out, int out_size) {
    const float* x  = (const float*)d_in[0];
    const float* W1 = (const float*)d_in[1];
    const float* b1 = (const float*)d_in[2];
    const float* W2 = (const float*)d_in[3];
    const float* b2 = (const float*)d_in[4];
    const int* src1 = (const int*)d_in[5];
    const int* dst1 = (const int*)d_in[6];
    const int* src2 = (const int*)d_in[7];
    const int* dst2 = (const int*)d_in[8];
    float* out = (float*)d_out;

    int E1 = in_sizes[5];
    int E2 = in_sizes[7];

    int* cnt1; cudaGetSymbolAddress((void**)&cnt1, g_cnt1);
    int* offs1; cudaGetSymbolAddress((void**)&offs1, g_offs1);
    int* cur1; cudaGetSymbolAddress((void**)&cur1, g_cur1);
    int* part1; cudaGetSymbolAddress((void**)&part1, g_part1);
    int* csr1; cudaGetSymbolAddress((void**)&csr1, g_csr1);
    int* cnt2; cudaGetSymbolAddress((void**)&cnt2, g_cnt2);
    int* offs2; cudaGetSymbolAddress((void**)&offs2, g_offs2);
    int* cur2; cudaGetSymbolAddress((void**)&cur2, g_cur2);
    int* part2; cudaGetSymbolAddress((void**)&part2, g_part2);
    int* csr2; cudaGetSymbolAddress((void**)&csr2, g_csr2);

    int nb1 = (N1 + SCAN_B - 1) / SCAN_B;   // 98
    int nb2 = (N2 + SCAN_B - 1) / SCAN_B;   // 10

    k_zero<<<(N1 + 255) / 256, 256>>>();
    k_project<<<(N0 + 255) / 256, 256>>>(x, W1);

    // layer-1 CSR
    k_hist<<<(E1 + 255) / 256, 256>>>(dst1, E1, cnt1);
    k_scan_block<<<nb1, SCAN_B>>>(cnt1, offs1, part1, N1);
    k_scan_partials<<<1, 128>>>(part1, nb1);
    k_scan_add<<<nb1, SCAN_B>>>(offs1, cur1, part1, N1);
    k_permute<<<(E1 + 255) / 256, 256>>>(src1, dst1, E1, cur1, csr1);
    k_gather1<<<(N1 + 127) / 128, 128>>>(b1);

    // layer-2 CSR
    k_hist<<<(E2 + 255) / 256, 256>>>(dst2, E2, cnt2);
    k_scan_block<<<nb2, SCAN_B>>>(cnt2, offs2, part2, N2);
    k_scan_partials<<<1, 128>>>(part2, nb2);
    k_scan_add<<<nb2, SCAN_B>>>(offs2, cur2, part2, N2);
    k_permute<<<(E2 + 255) / 256, 256>>>(src2, dst2, E2, cur2, csr2);
    k_gather2<<<(N2 + 127) / 128, 128>>>();

    k_out<<<(N2 + 7) / 8, 256>>>(W2, b2, out);
}